// round 2
// baseline (speedup 1.0000x reference)
#include <cuda_runtime.h>

#define BATCH   8192
#define OUT_N   4096
#define K_DIM   4096
#define SHOTS   1000

// Scratch for per-row quantum expectation (no device allocation allowed).
__device__ float g_expect[BATCH];

// ---------------------------------------------------------------------------
// Kernel 1: per-row expectation of outcomes. Exact integer sum, then scale by
// 1/(SHOTS * 15).  One block per batch row.
// ---------------------------------------------------------------------------
__global__ __launch_bounds__(256) void expect_kernel(const int* __restrict__ q) {
    const int row = blockIdx.x;
    const int* p = q + (long long)row * SHOTS;
    int sum = 0;
    for (int i = threadIdx.x; i < SHOTS; i += 256) sum += p[i];

    // warp reduce
    #pragma unroll
    for (int off = 16; off; off >>= 1) sum += __shfl_down_sync(0xffffffffu, sum, off);

    __shared__ int ssum[8];
    if ((threadIdx.x & 31) == 0) ssum[threadIdx.x >> 5] = sum;
    __syncthreads();
    if (threadIdx.x < 8) {
        int v = ssum[threadIdx.x];
        #pragma unroll
        for (int off = 4; off; off >>= 1) v += __shfl_down_sync(0xffu, v, off);
        if (threadIdx.x == 0)
            g_expect[row] = (float)v * (1.0f / (15.0f * (float)SHOTS));
    }
}

// ---------------------------------------------------------------------------
// Kernel 2: fp32 tiled GEMM  out[b,o] = sum_k x[b,k]*W[o,k] + bias[o] + e[b]
// BM=BN=128, BK=16, 256 threads, 8x8 register tile per thread.
// Both x and W are K-major (row-major [rows, K]) -> NT gemm, coalesced loads.
// ---------------------------------------------------------------------------
__global__ __launch_bounds__(256) void sgemm_kernel(
    const float* __restrict__ x,
    const float* __restrict__ W,
    const float* __restrict__ bias,
    float* __restrict__ out)
{
    __shared__ float As[16][128];   // As[k][m]
    __shared__ float Bs[16][128];   // Bs[k][n]

    const int bm  = blockIdx.y * 128;   // batch-row base
    const int bn  = blockIdx.x * 128;   // out-col base
    const int tid = threadIdx.x;

    // compute-thread layout: 16 x 16 threads, each owns 8x8 outputs
    const int tx = tid & 15;            // col group
    const int ty = tid >> 4;            // row group

    // loader layout: each thread loads 2 float4 from x and 2 from W
    const int lrow = tid >> 2;          // 0..63
    const int lcol = (tid & 3) << 2;    // 0,4,8,12

    const float* xA0 = x + (long long)(bm + lrow)      * K_DIM + lcol;
    const float* xA1 = x + (long long)(bm + lrow + 64) * K_DIM + lcol;
    const float* wB0 = W + (long long)(bn + lrow)      * K_DIM + lcol;
    const float* wB1 = W + (long long)(bn + lrow + 64) * K_DIM + lcol;

    float acc[8][8];
    #pragma unroll
    for (int i = 0; i < 8; i++)
        #pragma unroll
        for (int j = 0; j < 8; j++) acc[i][j] = 0.0f;

    for (int k0 = 0; k0 < K_DIM; k0 += 16) {
        const float4 a0 = *(const float4*)(xA0 + k0);
        const float4 a1 = *(const float4*)(xA1 + k0);
        const float4 b0 = *(const float4*)(wB0 + k0);
        const float4 b1 = *(const float4*)(wB1 + k0);

        __syncthreads();   // previous tile fully consumed

        As[lcol + 0][lrow] = a0.x;  As[lcol + 1][lrow] = a0.y;
        As[lcol + 2][lrow] = a0.z;  As[lcol + 3][lrow] = a0.w;
        As[lcol + 0][lrow + 64] = a1.x;  As[lcol + 1][lrow + 64] = a1.y;
        As[lcol + 2][lrow + 64] = a1.z;  As[lcol + 3][lrow + 64] = a1.w;

        Bs[lcol + 0][lrow] = b0.x;  Bs[lcol + 1][lrow] = b0.y;
        Bs[lcol + 2][lrow] = b0.z;  Bs[lcol + 3][lrow] = b0.w;
        Bs[lcol + 0][lrow + 64] = b1.x;  Bs[lcol + 1][lrow + 64] = b1.y;
        Bs[lcol + 2][lrow + 64] = b1.z;  Bs[lcol + 3][lrow + 64] = b1.w;

        __syncthreads();

        #pragma unroll
        for (int kk = 0; kk < 16; kk++) {
            float ar[8], br[8];
            *(float4*)(ar + 0) = *(const float4*)&As[kk][ty * 8 + 0];
            *(float4*)(ar + 4) = *(const float4*)&As[kk][ty * 8 + 4];
            *(float4*)(br + 0) = *(const float4*)&Bs[kk][tx * 8 + 0];
            *(float4*)(br + 4) = *(const float4*)&Bs[kk][tx * 8 + 4];
            #pragma unroll
            for (int i = 0; i < 8; i++)
                #pragma unroll
                for (int j = 0; j < 8; j++)
                    acc[i][j] = fmaf(ar[i], br[j], acc[i][j]);
        }
    }

    // epilogue: + bias[col] + expect[row]
    float bv[8];
    *(float4*)(bv + 0) = *(const float4*)&bias[bn + tx * 8 + 0];
    *(float4*)(bv + 4) = *(const float4*)&bias[bn + tx * 8 + 4];

    #pragma unroll
    for (int i = 0; i < 8; i++) {
        const int row = bm + ty * 8 + i;
        const float e = g_expect[row];
        float4 o0, o1;
        o0.x = acc[i][0] + bv[0] + e;  o0.y = acc[i][1] + bv[1] + e;
        o0.z = acc[i][2] + bv[2] + e;  o0.w = acc[i][3] + bv[3] + e;
        o1.x = acc[i][4] + bv[4] + e;  o1.y = acc[i][5] + bv[5] + e;
        o1.z = acc[i][6] + bv[6] + e;  o1.w = acc[i][7] + bv[7] + e;
        float* po = out + (long long)row * OUT_N + bn + tx * 8;
        *(float4*)(po + 0) = o0;
        *(float4*)(po + 4) = o1;
    }
}

// ---------------------------------------------------------------------------
extern "C" void kernel_launch(void* const* d_in, const int* in_sizes, int n_in,
                              void* d_out, int out_size) {
    const float* x    = (const float*)d_in[0];   // [8192, 4096]
    const float* W    = (const float*)d_in[1];   // [4096, 4096]
    const float* bias = (const float*)d_in[2];   // [4096]
    const int*   q    = (const int*)d_in[3];     // [8192, 1000]
    float* out = (float*)d_out;                  // [8192, 4096]

    expect_kernel<<<BATCH, 256>>>(q);

    dim3 grid(OUT_N / 128, BATCH / 128);   // (32, 64)
    sgemm_kernel<<<grid, 256>>>(x, W, bias, out);
}

// round 5
// speedup vs baseline: 2.5932x; 2.5932x over previous
#include <cuda_runtime.h>
#include <cuda_bf16.h>
#include <cstdint>

#define BATCH 8192
#define OUT_N 4096
#define KD    4096
#define SHOTS 1000

#define BM 128
#define BN 128
#define BK 64                       // K elems per stage (=128 bytes per row)
#define STAGES 3
#define KBLK (KD / BK)              // 64
#define NITER (3 * KBLK)            // 192: segments hi*hi, hi*lo, lo*hi
#define STAGE_BYTES (BM * 128 + BN * 128)   // 16KB A + 16KB B = 32768
#define SMEM_ALLOC (STAGES * STAGE_BYTES + 1024)

// ---- scratch (no device allocation allowed -> __device__ globals) ----
__device__ __align__(256) __nv_bfloat16 g_xhi[BATCH * KD];
__device__ __align__(256) __nv_bfloat16 g_xlo[BATCH * KD];
__device__ __align__(256) __nv_bfloat16 g_whi[OUT_N * KD];
__device__ __align__(256) __nv_bfloat16 g_wlo[OUT_N * KD];
__device__ float g_expect[BATCH];

// ---------------------------------------------------------------------------
__device__ __forceinline__ uint32_t smem_to_u32(const void* p) {
    uint32_t a;
    asm("{ .reg .u64 t; cvta.to.shared.u64 t, %1; cvt.u32.u64 %0, t; }" : "=r"(a) : "l"(p));
    return a;
}
#define SWZ(o) ((o) ^ (((o) >> 3) & 0x70))

__device__ __forceinline__ void cp_async16(uint32_t dst, const void* src) {
    asm volatile("cp.async.cg.shared.global [%0], [%1], 16;" :: "r"(dst), "l"(src));
}
#define CP_COMMIT() asm volatile("cp.async.commit_group;" ::: "memory")
#define CP_WAIT1()  asm volatile("cp.async.wait_group 1;"  ::: "memory")

__device__ __forceinline__ void ldm_x4(uint32_t* r, uint32_t addr) {
    asm volatile("ldmatrix.sync.aligned.m8n8.x4.shared.b16 {%0,%1,%2,%3}, [%4];"
                 : "=r"(r[0]), "=r"(r[1]), "=r"(r[2]), "=r"(r[3]) : "r"(addr));
}

__device__ __forceinline__ void mma16816(float* c, const uint32_t* a, uint32_t b0, uint32_t b1) {
    asm volatile(
        "mma.sync.aligned.m16n8k16.row.col.f32.bf16.bf16.f32 "
        "{%0,%1,%2,%3}, {%4,%5,%6,%7}, {%8,%9}, {%0,%1,%2,%3};"
        : "+f"(c[0]), "+f"(c[1]), "+f"(c[2]), "+f"(c[3])
        : "r"(a[0]), "r"(a[1]), "r"(a[2]), "r"(a[3]), "r"(b0), "r"(b1));
}

// ---------------------------------------------------------------------------
// expectation of quantum outcomes, one block per row
// ---------------------------------------------------------------------------
__global__ __launch_bounds__(256) void expect_kernel(const int* __restrict__ q) {
    const int row = blockIdx.x;
    const int* p = q + (long long)row * SHOTS;
    int sum = 0;
    for (int i = threadIdx.x; i < SHOTS; i += 256) sum += p[i];
    #pragma unroll
    for (int off = 16; off; off >>= 1) sum += __shfl_down_sync(0xffffffffu, sum, off);
    __shared__ int ssum[8];
    if ((threadIdx.x & 31) == 0) ssum[threadIdx.x >> 5] = sum;
    __syncthreads();
    if (threadIdx.x < 8) {
        int v = ssum[threadIdx.x];
        #pragma unroll
        for (int off = 4; off; off >>= 1) v += __shfl_down_sync(0xffu, v, off);
        if (threadIdx.x == 0)
            g_expect[row] = (float)v * (1.0f / (15.0f * (float)SHOTS));
    }
}

// ---------------------------------------------------------------------------
// fp32 -> bf16 hi/lo split converters
// ---------------------------------------------------------------------------
__device__ __forceinline__ void split4(const float4 v, uint2* hi2, uint2* lo2) {
    __nv_bfloat16 h0 = __float2bfloat16(v.x);
    __nv_bfloat16 h1 = __float2bfloat16(v.y);
    __nv_bfloat16 h2 = __float2bfloat16(v.z);
    __nv_bfloat16 h3 = __float2bfloat16(v.w);
    __nv_bfloat162 a = __halves2bfloat162(h0, h1);
    __nv_bfloat162 b = __halves2bfloat162(h2, h3);
    uint2 hv; hv.x = *(const uint32_t*)&a; hv.y = *(const uint32_t*)&b;
    __nv_bfloat162 c = __halves2bfloat162(__float2bfloat16(v.x - __bfloat162float(h0)),
                                          __float2bfloat16(v.y - __bfloat162float(h1)));
    __nv_bfloat162 d = __halves2bfloat162(__float2bfloat16(v.z - __bfloat162float(h2)),
                                          __float2bfloat16(v.w - __bfloat162float(h3)));
    uint2 lv; lv.x = *(const uint32_t*)&c; lv.y = *(const uint32_t*)&d;
    *hi2 = hv; *lo2 = lv;
}

__global__ __launch_bounds__(256) void split_x_kernel(const float4* __restrict__ src) {
    const int n4 = BATCH * KD / 4;
    uint2* hi = reinterpret_cast<uint2*>(g_xhi);
    uint2* lo = reinterpret_cast<uint2*>(g_xlo);
    for (int i = blockIdx.x * 256 + threadIdx.x; i < n4; i += gridDim.x * 256) {
        uint2 h, l;
        split4(src[i], &h, &l);
        hi[i] = h; lo[i] = l;
    }
}

__global__ __launch_bounds__(256) void split_w_kernel(const float4* __restrict__ src) {
    const int n4 = OUT_N * KD / 4;
    uint2* hi = reinterpret_cast<uint2*>(g_whi);
    uint2* lo = reinterpret_cast<uint2*>(g_wlo);
    for (int i = blockIdx.x * 256 + threadIdx.x; i < n4; i += gridDim.x * 256) {
        uint2 h, l;
        split4(src[i], &h, &l);
        hi[i] = h; lo[i] = l;
    }
}

// ---------------------------------------------------------------------------
// mma.sync bf16 GEMM: out = (xhi+xlo)(whi+wlo)^T + bias + expect (lo*lo dropped)
// 128x128 tile, BK=64, 3-stage cp.async pipeline, 8 warps (2x4), 64x32/warp.
// ---------------------------------------------------------------------------
__global__ __launch_bounds__(256, 1) void gemm_kernel(const float* __restrict__ bias,
                                                      float* __restrict__ out) {
    extern __shared__ char smem_raw[];
    uint32_t sbase = (smem_to_u32(smem_raw) + 1023u) & ~1023u;   // SW128 needs 1KB align
    const int tid  = threadIdx.x;
    const int wid  = tid >> 5;
    const int lane = tid & 31;

    // --- rasterization with GROUP_M supergrouping ---
    const int num_pid_n = OUT_N / BN;   // 32
    const int num_pid_m = BATCH / BM;   // 64
    const int GROUP_M = 8;
    int pid = blockIdx.x;
    int num_in_group = GROUP_M * num_pid_n;
    int group_id = pid / num_in_group;
    int first_m = group_id * GROUP_M;
    int gsz = min(num_pid_m - first_m, GROUP_M);
    int pid_m = first_m + (pid % gsz);
    int pid_n = (pid % num_in_group) / gsz;
    const int bm = pid_m * BM;
    const int bn = pid_n * BN;

    const int wm = wid & 1;     // 0..1 : 64-row band
    const int wn = wid >> 1;    // 0..3 : 32-col band

    // --- loader precompute: 2048 16B chunks/stage, 8 per thread ---
    uint32_t soff[8];    // swizzled offset within stage
    uint32_t goff[8];    // global element offset (row*KD + kchunk*8)
    bool     isA[8];
    #pragma unroll
    for (int u = 0; u < 8; ++u) {
        int idx = tid + 256 * u;
        bool a = idx < (BM * 8);
        int r = a ? (idx >> 3) : ((idx - BM * 8) >> 3);
        int c = idx & 7;
        isA[u] = a;
        uint32_t bo = (uint32_t)(r * 128 + c * 16);
        soff[u] = (a ? 0u : (uint32_t)(BM * 128)) + SWZ(bo);
        goff[u] = (uint32_t)(((a ? bm : bn) + r) * KD + c * 8);
    }

    auto issue_loads = [&](int j) {
        const int slot = j % STAGES;
        const char* aseg = (const char*)((j < 2 * KBLK) ? g_xhi : g_xlo);
        const char* bseg = (const char*)((j >= KBLK && j < 2 * KBLK) ? g_wlo : g_whi);
        const uint32_t kboff = (uint32_t)(j & (KBLK - 1)) * (BK * 2);
        const uint32_t sb = sbase + slot * STAGE_BYTES;
        #pragma unroll
        for (int u = 0; u < 8; ++u) {
            const char* src = (isA[u] ? aseg : bseg) + (size_t)goff[u] * 2 + kboff;
            cp_async16(sb + soff[u], src);
        }
        CP_COMMIT();
    };

    // --- per-lane ldmatrix base offsets (stage-relative, before swizzle) ---
    const int g  = lane >> 3;
    const int lr = lane & 7;
    // A: row = wm*64 + mi*16 + lr + (g&1)*8 ; col = ks*32 + (g>>1)*16
    const int a_row_base = wm * 64 + lr + (g & 1) * 8;
    const int a_col_base = (g >> 1) * 16;
    // B: row = wn*32 + np*16 + lr + (g>>1)*8 ; col = ks*32 + (g&1)*16
    const int b_row_base = wn * 32 + lr + (g >> 1) * 8;
    const int b_col_base = (g & 1) * 16;

    float acc[4][4][4];
    #pragma unroll
    for (int mi = 0; mi < 4; mi++)
        #pragma unroll
        for (int ni = 0; ni < 4; ni++)
            #pragma unroll
            for (int k = 0; k < 4; k++) acc[mi][ni][k] = 0.0f;

    issue_loads(0);
    issue_loads(1);

    for (int it = 0; it < NITER; ++it) {
        const int slot = it % STAGES;
        CP_WAIT1();
        __syncthreads();

        if (it + 2 < NITER) issue_loads(it + 2);
        else                CP_COMMIT();        // empty group keeps wait count valid

        const uint32_t sA = sbase + slot * STAGE_BYTES;
        const uint32_t sB = sA + BM * 128;

        #pragma unroll
        for (int ks = 0; ks < 4; ++ks) {
            uint32_t a[4][4];
            #pragma unroll
            for (int mi = 0; mi < 4; ++mi) {
                uint32_t off = (uint32_t)((a_row_base + mi * 16) * 128 +
                                          ks * 32 + a_col_base);
                ldm_x4(a[mi], sA + SWZ(off));
            }
            uint32_t b[2][4];
            #pragma unroll
            for (int np = 0; np < 2; ++np) {
                uint32_t off = (uint32_t)((b_row_base + np * 16) * 128 +
                                          ks * 32 + b_col_base);
                ldm_x4(b[np], sB + SWZ(off));
            }
            #pragma unroll
            for (int mi = 0; mi < 4; ++mi)
                #pragma unroll
                for (int ni = 0; ni < 4; ++ni)
                    mma16816(acc[mi][ni], a[mi],
                             b[ni >> 1][2 * (ni & 1)], b[ni >> 1][2 * (ni & 1) + 1]);
        }
    }

    // --- epilogue: + bias[col] + expect[row] ---
    #pragma unroll
    for (int mi = 0; mi < 4; ++mi) {
        const int r0 = bm + wm * 64 + mi * 16 + (lane >> 2);
        const float e0 = g_expect[r0];
        const float e1 = g_expect[r0 + 8];
        float* o0 = out + (size_t)r0 * OUT_N;
        float* o1 = out + (size_t)(r0 + 8) * OUT_N;
        #pragma unroll
        for (int ni = 0; ni < 4; ++ni) {
            const int c = bn + wn * 32 + ni * 8 + (lane & 3) * 2;
            const float b0 = __ldg(&bias[c]);
            const float b1 = __ldg(&bias[c + 1]);
            float2 v0, v1;
            v0.x = acc[mi][ni][0] + b0 + e0;
            v0.y = acc[mi][ni][1] + b1 + e0;
            v1.x = acc[mi][ni][2] + b0 + e1;
            v1.y = acc[mi][ni][3] + b1 + e1;
            *(float2*)(o0 + c) = v0;
            *(float2*)(o1 + c) = v1;
        }
    }
}

// ---------------------------------------------------------------------------
extern "C" void kernel_launch(void* const* d_in, const int* in_sizes, int n_in,
                              void* d_out, int out_size) {
    const float* x    = (const float*)d_in[0];   // [8192, 4096]
    const float* W    = (const float*)d_in[1];   // [4096, 4096]
    const float* bias = (const float*)d_in[2];   // [4096]
    const int*   q    = (const int*)d_in[3];     // [8192, 1000]
    float* out = (float*)d_out;                  // [8192, 4096]

    cudaFuncSetAttribute(gemm_kernel, cudaFuncAttributeMaxDynamicSharedMemorySize, SMEM_ALLOC);

    expect_kernel<<<BATCH, 256>>>(q);
    split_x_kernel<<<8192, 256>>>((const float4*)x);
    split_w_kernel<<<4096, 256>>>((const float4*)W);

    const int grid = (BATCH / BM) * (OUT_N / BN);   // 2048
    gemm_kernel<<<grid, 256, SMEM_ALLOC>>>(bias, out);
}

// round 6
// speedup vs baseline: 4.5219x; 1.7438x over previous
#include <cuda_runtime.h>
#include <cuda_fp16.h>
#include <cstdint>

#define BATCH 8192
#define OUT_N 4096
#define KD    4096
#define SHOTS 1000

#define BM 128
#define BN 256
#define BK 64                       // K elems per stage (=128 bytes per row)
#define STAGES 3
#define KBLK (KD / BK)              // 64
#define NITER (2 * KBLK)            // 128: segments xhi*W, xlo*W
#define STAGE_BYTES (BM * 128 + BN * 128)   // 16KB A + 32KB B = 49152
#define SMEM_ALLOC (STAGES * STAGE_BYTES + 1024)

// ---- scratch (no device allocation allowed -> __device__ globals) ----
__device__ __align__(256) __half g_xhi[BATCH * KD];
__device__ __align__(256) __half g_xlo[BATCH * KD];
__device__ __align__(256) __half g_w[OUT_N * KD];
__device__ float g_expect[BATCH];

// ---------------------------------------------------------------------------
__device__ __forceinline__ uint32_t smem_to_u32(const void* p) {
    uint32_t a;
    asm("{ .reg .u64 t; cvta.to.shared.u64 t, %1; cvt.u32.u64 %0, t; }" : "=r"(a) : "l"(p));
    return a;
}
#define SWZ(o) ((o) ^ (((o) >> 3) & 0x70))

__device__ __forceinline__ void cp_async16(uint32_t dst, const void* src) {
    asm volatile("cp.async.cg.shared.global [%0], [%1], 16;" :: "r"(dst), "l"(src));
}
#define CP_COMMIT() asm volatile("cp.async.commit_group;" ::: "memory")
#define CP_WAIT1()  asm volatile("cp.async.wait_group 1;"  ::: "memory")

__device__ __forceinline__ void ldm_x4(uint32_t* r, uint32_t addr) {
    asm volatile("ldmatrix.sync.aligned.m8n8.x4.shared.b16 {%0,%1,%2,%3}, [%4];"
                 : "=r"(r[0]), "=r"(r[1]), "=r"(r[2]), "=r"(r[3]) : "r"(addr));
}

__device__ __forceinline__ void mma16816(float* c, const uint32_t* a, uint32_t b0, uint32_t b1) {
    asm volatile(
        "mma.sync.aligned.m16n8k16.row.col.f32.f16.f16.f32 "
        "{%0,%1,%2,%3}, {%4,%5,%6,%7}, {%8,%9}, {%0,%1,%2,%3};"
        : "+f"(c[0]), "+f"(c[1]), "+f"(c[2]), "+f"(c[3])
        : "r"(a[0]), "r"(a[1]), "r"(a[2]), "r"(a[3]), "r"(b0), "r"(b1));
}

// ---------------------------------------------------------------------------
// expectation of quantum outcomes, one block per row
// ---------------------------------------------------------------------------
__global__ __launch_bounds__(256) void expect_kernel(const int* __restrict__ q) {
    const int row = blockIdx.x;
    const int* p = q + (long long)row * SHOTS;
    int sum = 0;
    for (int i = threadIdx.x; i < SHOTS; i += 256) sum += p[i];
    #pragma unroll
    for (int off = 16; off; off >>= 1) sum += __shfl_down_sync(0xffffffffu, sum, off);
    __shared__ int ssum[8];
    if ((threadIdx.x & 31) == 0) ssum[threadIdx.x >> 5] = sum;
    __syncthreads();
    if (threadIdx.x < 8) {
        int v = ssum[threadIdx.x];
        #pragma unroll
        for (int off = 4; off; off >>= 1) v += __shfl_down_sync(0xffu, v, off);
        if (threadIdx.x == 0)
            g_expect[row] = (float)v * (1.0f / (15.0f * (float)SHOTS));
    }
}

// ---------------------------------------------------------------------------
// fp32 -> fp16 converters: x split hi/lo (22 effective bits), W single fp16
// ---------------------------------------------------------------------------
__global__ __launch_bounds__(256) void split_x_kernel(const float4* __restrict__ src) {
    const int n4 = BATCH * KD / 4;
    uint2* hi = reinterpret_cast<uint2*>(g_xhi);
    uint2* lo = reinterpret_cast<uint2*>(g_xlo);
    for (int i = blockIdx.x * 256 + threadIdx.x; i < n4; i += gridDim.x * 256) {
        float4 v = src[i];
        __half h0 = __float2half_rn(v.x), h1 = __float2half_rn(v.y);
        __half h2 = __float2half_rn(v.z), h3 = __float2half_rn(v.w);
        __half2 a = __halves2half2(h0, h1), b = __halves2half2(h2, h3);
        uint2 hv; hv.x = *(const uint32_t*)&a; hv.y = *(const uint32_t*)&b;
        __half2 c = __halves2half2(__float2half_rn(v.x - __half2float(h0)),
                                   __float2half_rn(v.y - __half2float(h1)));
        __half2 d = __halves2half2(__float2half_rn(v.z - __half2float(h2)),
                                   __float2half_rn(v.w - __half2float(h3)));
        uint2 lv; lv.x = *(const uint32_t*)&c; lv.y = *(const uint32_t*)&d;
        hi[i] = hv; lo[i] = lv;
    }
}

__global__ __launch_bounds__(256) void conv_w_kernel(const float4* __restrict__ src) {
    const int n4 = OUT_N * KD / 4;
    uint2* w = reinterpret_cast<uint2*>(g_w);
    for (int i = blockIdx.x * 256 + threadIdx.x; i < n4; i += gridDim.x * 256) {
        float4 v = src[i];
        __half2 a = __halves2half2(__float2half_rn(v.x), __float2half_rn(v.y));
        __half2 b = __halves2half2(__float2half_rn(v.z), __float2half_rn(v.w));
        uint2 hv; hv.x = *(const uint32_t*)&a; hv.y = *(const uint32_t*)&b;
        w[i] = hv;
    }
}

// ---------------------------------------------------------------------------
// mma.sync fp16 GEMM: out = (xhi+xlo) W^T + bias + expect
// 128x256 tile, BK=64, 3-stage cp.async pipeline, 8 warps (2x4), 64x64/warp.
// ---------------------------------------------------------------------------
__global__ __launch_bounds__(256, 1) void gemm_kernel(const float* __restrict__ bias,
                                                      float* __restrict__ out) {
    extern __shared__ char smem_raw[];
    uint32_t sbase = (smem_to_u32(smem_raw) + 1023u) & ~1023u;
    const int tid  = threadIdx.x;
    const int wid  = tid >> 5;
    const int lane = tid & 31;

    // --- rasterization with GROUP_M supergrouping ---
    const int num_pid_n = OUT_N / BN;   // 16
    const int num_pid_m = BATCH / BM;   // 64
    const int GROUP_M = 8;
    int pid = blockIdx.x;
    int num_in_group = GROUP_M * num_pid_n;
    int group_id = pid / num_in_group;
    int first_m = group_id * GROUP_M;
    int gsz = min(num_pid_m - first_m, GROUP_M);
    int pid_m = first_m + (pid % gsz);
    int pid_n = (pid % num_in_group) / gsz;
    const int bm = pid_m * BM;
    const int bn = pid_n * BN;

    const int wm = wid & 1;     // 0..1 : 64-row band
    const int wn = wid >> 1;    // 0..3 : 64-col band

    // --- loader precompute: 3072 16B chunks/stage, 12 per thread ---
    uint32_t soff[12];
    uint32_t goff[12];
    bool     isA[12];
    #pragma unroll
    for (int u = 0; u < 12; ++u) {
        int idx = tid + 256 * u;
        bool a = idx < (BM * 8);
        int r = a ? (idx >> 3) : ((idx - BM * 8) >> 3);
        int c = idx & 7;
        isA[u] = a;
        uint32_t bo = (uint32_t)(r * 128 + c * 16);
        soff[u] = (a ? 0u : (uint32_t)(BM * 128)) + SWZ(bo);
        goff[u] = (uint32_t)(((a ? bm : bn) + r) * KD + c * 8);
    }

    auto issue_loads = [&](int j) {
        const int slot = j % STAGES;
        const char* aseg = (const char*)((j < KBLK) ? g_xhi : g_xlo);
        const char* bseg = (const char*)g_w;
        const uint32_t kboff = (uint32_t)(j & (KBLK - 1)) * (BK * 2);
        const uint32_t sb = sbase + slot * STAGE_BYTES;
        #pragma unroll
        for (int u = 0; u < 12; ++u) {
            const char* src = (isA[u] ? aseg : bseg) + (size_t)goff[u] * 2 + kboff;
            cp_async16(sb + soff[u], src);
        }
        CP_COMMIT();
    };

    // --- per-lane ldmatrix base offsets (stage-relative, before swizzle) ---
    const int g  = lane >> 3;
    const int lr = lane & 7;
    const int a_row_base = wm * 64 + lr + (g & 1) * 8;   // + mi*16
    const int a_col_base = (g >> 1) * 16;                // + ks*32
    const int b_row_base = wn * 64 + lr + (g >> 1) * 8;  // + np*16
    const int b_col_base = (g & 1) * 16;                 // + ks*32

    float acc[4][8][4];
    #pragma unroll
    for (int mi = 0; mi < 4; mi++)
        #pragma unroll
        for (int ni = 0; ni < 8; ni++)
            #pragma unroll
            for (int k = 0; k < 4; k++) acc[mi][ni][k] = 0.0f;

    issue_loads(0);
    issue_loads(1);

    for (int it = 0; it < NITER; ++it) {
        const int slot = it % STAGES;
        CP_WAIT1();
        __syncthreads();

        if (it + 2 < NITER) issue_loads(it + 2);
        else                CP_COMMIT();        // empty group keeps wait count valid

        const uint32_t sA = sbase + slot * STAGE_BYTES;
        const uint32_t sB = sA + BM * 128;

        #pragma unroll
        for (int ks = 0; ks < 4; ++ks) {
            uint32_t a[4][4];
            #pragma unroll
            for (int mi = 0; mi < 4; ++mi) {
                uint32_t off = (uint32_t)((a_row_base + mi * 16) * 128 +
                                          ks * 32 + a_col_base);
                ldm_x4(a[mi], sA + SWZ(off));
            }
            uint32_t b[4][4];
            #pragma unroll
            for (int np = 0; np < 4; ++np) {
                uint32_t off = (uint32_t)((b_row_base + np * 16) * 128 +
                                          ks * 32 + b_col_base);
                ldm_x4(b[np], sB + SWZ(off));
            }
            #pragma unroll
            for (int mi = 0; mi < 4; ++mi)
                #pragma unroll
                for (int ni = 0; ni < 8; ++ni)
                    mma16816(acc[mi][ni], a[mi],
                             b[ni >> 1][2 * (ni & 1)], b[ni >> 1][2 * (ni & 1) + 1]);
        }
    }

    // --- epilogue: + bias[col] + expect[row] ---
    #pragma unroll
    for (int mi = 0; mi < 4; ++mi) {
        const int r0 = bm + wm * 64 + mi * 16 + (lane >> 2);
        const float e0 = g_expect[r0];
        const float e1 = g_expect[r0 + 8];
        float* o0 = out + (size_t)r0 * OUT_N;
        float* o1 = out + (size_t)(r0 + 8) * OUT_N;
        #pragma unroll
        for (int ni = 0; ni < 8; ++ni) {
            const int c = bn + wn * 64 + ni * 8 + (lane & 3) * 2;
            const float b0 = __ldg(&bias[c]);
            const float b1 = __ldg(&bias[c + 1]);
            float2 v0, v1;
            v0.x = acc[mi][ni][0] + b0 + e0;
            v0.y = acc[mi][ni][1] + b1 + e0;
            v1.x = acc[mi][ni][2] + b0 + e1;
            v1.y = acc[mi][ni][3] + b1 + e1;
            *(float2*)(o0 + c) = v0;
            *(float2*)(o1 + c) = v1;
        }
    }
}

// ---------------------------------------------------------------------------
extern "C" void kernel_launch(void* const* d_in, const int* in_sizes, int n_in,
                              void* d_out, int out_size) {
    const float* x    = (const float*)d_in[0];   // [8192, 4096]
    const float* W    = (const float*)d_in[1];   // [4096, 4096]
    const float* bias = (const float*)d_in[2];   // [4096]
    const int*   q    = (const int*)d_in[3];     // [8192, 1000]
    float* out = (float*)d_out;                  // [8192, 4096]

    cudaFuncSetAttribute(gemm_kernel, cudaFuncAttributeMaxDynamicSharedMemorySize, SMEM_ALLOC);

    expect_kernel<<<BATCH, 256>>>(q);
    split_x_kernel<<<8192, 256>>>((const float4*)x);
    conv_w_kernel<<<4096, 256>>>((const float4*)W);

    const int grid = (BATCH / BM) * (OUT_N / BN);   // 1024
    gemm_kernel<<<grid, 256, SMEM_ALLOC>>>(bias, out);
}

// round 7
// speedup vs baseline: 8.7875x; 1.9433x over previous
#include <cuda_runtime.h>
#include <cuda_fp16.h>
#include <cstdint>

#define BATCH 8192
#define OUT_N 4096
#define KD    4096
#define SHOTS 1000

#define BM 128
#define BN 256
#define BK 64                       // K elems per stage (=128 bytes per row)
#define STAGES 4
#define KBLK (KD / BK)              // 64
#define NITER KBLK                  // 64: single fp16 pass
#define STAGE_BYTES (BM * 128 + BN * 128)   // 16KB A + 32KB B = 49152
#define SMEM_ALLOC (STAGES * STAGE_BYTES + 1024)   // 197632

// ---- scratch (no device allocation allowed -> __device__ globals) ----
__device__ __align__(256) __half g_x[BATCH * KD];
__device__ __align__(256) __half g_w[OUT_N * KD];
__device__ float g_expect[BATCH];

// ---------------------------------------------------------------------------
__device__ __forceinline__ uint32_t smem_to_u32(const void* p) {
    uint32_t a;
    asm("{ .reg .u64 t; cvta.to.shared.u64 t, %1; cvt.u32.u64 %0, t; }" : "=r"(a) : "l"(p));
    return a;
}
#define SWZ(o) ((o) ^ (((o) >> 3) & 0x70))

__device__ __forceinline__ void cp_async16(uint32_t dst, const void* src) {
    asm volatile("cp.async.cg.shared.global [%0], [%1], 16;" :: "r"(dst), "l"(src));
}
#define CP_COMMIT() asm volatile("cp.async.commit_group;" ::: "memory")
#define CP_WAIT2()  asm volatile("cp.async.wait_group 2;"  ::: "memory")

__device__ __forceinline__ void ldm_x4(uint32_t* r, uint32_t addr) {
    asm volatile("ldmatrix.sync.aligned.m8n8.x4.shared.b16 {%0,%1,%2,%3}, [%4];"
                 : "=r"(r[0]), "=r"(r[1]), "=r"(r[2]), "=r"(r[3]) : "r"(addr));
}

__device__ __forceinline__ void mma16816(float* c, const uint32_t* a, uint32_t b0, uint32_t b1) {
    asm volatile(
        "mma.sync.aligned.m16n8k16.row.col.f32.f16.f16.f32 "
        "{%0,%1,%2,%3}, {%4,%5,%6,%7}, {%8,%9}, {%0,%1,%2,%3};"
        : "+f"(c[0]), "+f"(c[1]), "+f"(c[2]), "+f"(c[3])
        : "r"(a[0]), "r"(a[1]), "r"(a[2]), "r"(a[3]), "r"(b0), "r"(b1));
}

// ---------------------------------------------------------------------------
// expectation of quantum outcomes, one block per row
// ---------------------------------------------------------------------------
__global__ __launch_bounds__(256) void expect_kernel(const int* __restrict__ q) {
    const int row = blockIdx.x;
    const int* p = q + (long long)row * SHOTS;
    int sum = 0;
    for (int i = threadIdx.x; i < SHOTS; i += 256) sum += p[i];
    #pragma unroll
    for (int off = 16; off; off >>= 1) sum += __shfl_down_sync(0xffffffffu, sum, off);
    __shared__ int ssum[8];
    if ((threadIdx.x & 31) == 0) ssum[threadIdx.x >> 5] = sum;
    __syncthreads();
    if (threadIdx.x < 8) {
        int v = ssum[threadIdx.x];
        #pragma unroll
        for (int off = 4; off; off >>= 1) v += __shfl_down_sync(0xffu, v, off);
        if (threadIdx.x == 0)
            g_expect[row] = (float)v * (1.0f / (15.0f * (float)SHOTS));
    }
}

// ---------------------------------------------------------------------------
// fp32 -> fp16 converters
// ---------------------------------------------------------------------------
__global__ __launch_bounds__(256) void conv_x_kernel(const float4* __restrict__ src) {
    const int n4 = BATCH * KD / 4;
    uint2* dst = reinterpret_cast<uint2*>(g_x);
    for (int i = blockIdx.x * 256 + threadIdx.x; i < n4; i += gridDim.x * 256) {
        float4 v = src[i];
        __half2 a = __halves2half2(__float2half_rn(v.x), __float2half_rn(v.y));
        __half2 b = __halves2half2(__float2half_rn(v.z), __float2half_rn(v.w));
        uint2 hv; hv.x = *(const uint32_t*)&a; hv.y = *(const uint32_t*)&b;
        dst[i] = hv;
    }
}

__global__ __launch_bounds__(256) void conv_w_kernel(const float4* __restrict__ src) {
    const int n4 = OUT_N * KD / 4;
    uint2* dst = reinterpret_cast<uint2*>(g_w);
    for (int i = blockIdx.x * 256 + threadIdx.x; i < n4; i += gridDim.x * 256) {
        float4 v = src[i];
        __half2 a = __halves2half2(__float2half_rn(v.x), __float2half_rn(v.y));
        __half2 b = __halves2half2(__float2half_rn(v.z), __float2half_rn(v.w));
        uint2 hv; hv.x = *(const uint32_t*)&a; hv.y = *(const uint32_t*)&b;
        dst[i] = hv;
    }
}

// ---------------------------------------------------------------------------
// mma.sync fp16 GEMM: out = x W^T + bias + expect   (single fp16 pass)
// 128x256 tile, BK=64, 4-stage cp.async pipeline, 8 warps (2x4), 64x64/warp.
// ---------------------------------------------------------------------------
__global__ __launch_bounds__(256, 1) void gemm_kernel(const float* __restrict__ bias,
                                                      float* __restrict__ out) {
    extern __shared__ char smem_raw[];
    uint32_t sbase = (smem_to_u32(smem_raw) + 1023u) & ~1023u;
    const int tid  = threadIdx.x;
    const int wid  = tid >> 5;
    const int lane = tid & 31;

    // --- rasterization with GROUP_M supergrouping ---
    const int num_pid_n = OUT_N / BN;   // 16
    const int num_pid_m = BATCH / BM;   // 64
    const int GROUP_M = 8;
    int pid = blockIdx.x;
    int num_in_group = GROUP_M * num_pid_n;
    int group_id = pid / num_in_group;
    int first_m = group_id * GROUP_M;
    int gsz = min(num_pid_m - first_m, GROUP_M);
    int pid_m = first_m + (pid % gsz);
    int pid_n = (pid % num_in_group) / gsz;
    const int bm = pid_m * BM;
    const int bn = pid_n * BN;

    const int wm = wid & 1;     // 0..1 : 64-row band
    const int wn = wid >> 1;    // 0..3 : 64-col band

    // --- loader precompute: 3072 16B chunks/stage, 12 per thread ---
    uint32_t soff[12];
    uint32_t goff[12];
    bool     isA[12];
    #pragma unroll
    for (int u = 0; u < 12; ++u) {
        int idx = tid + 256 * u;
        bool a = idx < (BM * 8);
        int r = a ? (idx >> 3) : ((idx - BM * 8) >> 3);
        int c = idx & 7;
        isA[u] = a;
        uint32_t bo = (uint32_t)(r * 128 + c * 16);
        soff[u] = (a ? 0u : (uint32_t)(BM * 128)) + SWZ(bo);
        goff[u] = (uint32_t)(((a ? bm : bn) + r) * KD + c * 8);
    }

    auto issue_loads = [&](int j) {
        const int slot = j & (STAGES - 1);
        const uint32_t kboff = (uint32_t)j * (BK * 2);
        const uint32_t sb = sbase + slot * STAGE_BYTES;
        #pragma unroll
        for (int u = 0; u < 12; ++u) {
            const char* src = (const char*)(isA[u] ? g_x : g_w) + (size_t)goff[u] * 2 + kboff;
            cp_async16(sb + soff[u], src);
        }
        CP_COMMIT();
    };

    // --- per-lane ldmatrix base offsets (stage-relative, before swizzle) ---
    const int g  = lane >> 3;
    const int lr = lane & 7;
    const int a_row_base = wm * 64 + lr + (g & 1) * 8;   // + mi*16
    const int a_col_base = (g >> 1) * 16;                // + ks*32
    const int b_row_base = wn * 64 + lr + (g >> 1) * 8;  // + np*16
    const int b_col_base = (g & 1) * 16;                 // + ks*32

    float acc[4][8][4];
    #pragma unroll
    for (int mi = 0; mi < 4; mi++)
        #pragma unroll
        for (int ni = 0; ni < 8; ni++)
            #pragma unroll
            for (int k = 0; k < 4; k++) acc[mi][ni][k] = 0.0f;

    issue_loads(0);
    issue_loads(1);
    issue_loads(2);

    for (int it = 0; it < NITER; ++it) {
        const int slot = it & (STAGES - 1);
        CP_WAIT2();
        __syncthreads();

        if (it + 3 < NITER) issue_loads(it + 3);
        else                CP_COMMIT();        // empty group keeps wait count valid

        const uint32_t sA = sbase + slot * STAGE_BYTES;
        const uint32_t sB = sA + BM * 128;

        #pragma unroll
        for (int ks = 0; ks < 4; ++ks) {
            uint32_t a[4][4];
            #pragma unroll
            for (int mi = 0; mi < 4; ++mi) {
                uint32_t off = (uint32_t)((a_row_base + mi * 16) * 128 +
                                          ks * 32 + a_col_base);
                ldm_x4(a[mi], sA + SWZ(off));
            }
            uint32_t b[4][4];
            #pragma unroll
            for (int np = 0; np < 4; ++np) {
                uint32_t off = (uint32_t)((b_row_base + np * 16) * 128 +
                                          ks * 32 + b_col_base);
                ldm_x4(b[np], sB + SWZ(off));
            }
            #pragma unroll
            for (int mi = 0; mi < 4; ++mi)
                #pragma unroll
                for (int ni = 0; ni < 8; ++ni)
                    mma16816(acc[mi][ni], a[mi],
                             b[ni >> 1][2 * (ni & 1)], b[ni >> 1][2 * (ni & 1) + 1]);
        }
    }

    // --- epilogue: + bias[col] + expect[row] ---
    #pragma unroll
    for (int mi = 0; mi < 4; ++mi) {
        const int r0 = bm + wm * 64 + mi * 16 + (lane >> 2);
        const float e0 = g_expect[r0];
        const float e1 = g_expect[r0 + 8];
        float* o0 = out + (size_t)r0 * OUT_N;
        float* o1 = out + (size_t)(r0 + 8) * OUT_N;
        #pragma unroll
        for (int ni = 0; ni < 8; ++ni) {
            const int c = bn + wn * 64 + ni * 8 + (lane & 3) * 2;
            const float b0 = __ldg(&bias[c]);
            const float b1 = __ldg(&bias[c + 1]);
            float2 v0, v1;
            v0.x = acc[mi][ni][0] + b0 + e0;
            v0.y = acc[mi][ni][1] + b1 + e0;
            v1.x = acc[mi][ni][2] + b0 + e1;
            v1.y = acc[mi][ni][3] + b1 + e1;
            *(float2*)(o0 + c) = v0;
            *(float2*)(o1 + c) = v1;
        }
    }
}

// ---------------------------------------------------------------------------
extern "C" void kernel_launch(void* const* d_in, const int* in_sizes, int n_in,
                              void* d_out, int out_size) {
    const float* x    = (const float*)d_in[0];   // [8192, 4096]
    const float* W    = (const float*)d_in[1];   // [4096, 4096]
    const float* bias = (const float*)d_in[2];   // [4096]
    const int*   q    = (const int*)d_in[3];     // [8192, 1000]
    float* out = (float*)d_out;                  // [8192, 4096]

    cudaFuncSetAttribute(gemm_kernel, cudaFuncAttributeMaxDynamicSharedMemorySize, SMEM_ALLOC);

    expect_kernel<<<BATCH, 256>>>(q);
    conv_x_kernel<<<8192, 256>>>((const float4*)x);
    conv_w_kernel<<<4096, 256>>>((const float4*)W);

    const int grid = (BATCH / BM) * (OUT_N / BN);   // 1024
    gemm_kernel<<<grid, 256, SMEM_ALLOC>>>(bias, out);
}

// round 8
// speedup vs baseline: 9.0360x; 1.0283x over previous
#include <cuda_runtime.h>
#include <cuda_fp16.h>
#include <cstdint>

#define BATCH 8192
#define OUT_N 4096
#define KD    4096
#define SHOTS 1000

#define BM 128
#define BN 128
#define BK 64                       // K elems per stage (=128 bytes per row)
#define STAGES 3
#define KBLK (KD / BK)              // 64
#define NITER KBLK                  // 64
#define STAGE_BYTES (BM * 128 + BN * 128)   // 16KB + 16KB = 32768
#define SMEM_ALLOC (STAGES * STAGE_BYTES + 1024)   // 99328

// ---- scratch (no device allocation allowed -> __device__ globals) ----
__device__ __align__(256) __half g_x[BATCH * KD];
__device__ __align__(256) __half g_w[OUT_N * KD];
__device__ float g_expect[BATCH];

// ---------------------------------------------------------------------------
__device__ __forceinline__ uint32_t smem_to_u32(const void* p) {
    uint32_t a;
    asm("{ .reg .u64 t; cvta.to.shared.u64 t, %1; cvt.u32.u64 %0, t; }" : "=r"(a) : "l"(p));
    return a;
}
#define SWZ(o) ((o) ^ (((o) >> 3) & 0x70))

__device__ __forceinline__ void cp_async16(uint32_t dst, const void* src) {
    asm volatile("cp.async.cg.shared.global [%0], [%1], 16;" :: "r"(dst), "l"(src));
}
#define CP_COMMIT() asm volatile("cp.async.commit_group;" ::: "memory")
#define CP_WAIT1()  asm volatile("cp.async.wait_group 1;"  ::: "memory")

__device__ __forceinline__ void ldm_x4(uint32_t* r, uint32_t addr) {
    asm volatile("ldmatrix.sync.aligned.m8n8.x4.shared.b16 {%0,%1,%2,%3}, [%4];"
                 : "=r"(r[0]), "=r"(r[1]), "=r"(r[2]), "=r"(r[3]) : "r"(addr));
}

__device__ __forceinline__ void mma16816(float* c, const uint32_t* a, uint32_t b0, uint32_t b1) {
    asm volatile(
        "mma.sync.aligned.m16n8k16.row.col.f32.f16.f16.f32 "
        "{%0,%1,%2,%3}, {%4,%5,%6,%7}, {%8,%9}, {%0,%1,%2,%3};"
        : "+f"(c[0]), "+f"(c[1]), "+f"(c[2]), "+f"(c[3])
        : "r"(a[0]), "r"(a[1]), "r"(a[2]), "r"(a[3]), "r"(b0), "r"(b1));
}

// ---------------------------------------------------------------------------
// expectation of quantum outcomes, one block per row
// ---------------------------------------------------------------------------
__global__ __launch_bounds__(256) void expect_kernel(const int* __restrict__ q) {
    const int row = blockIdx.x;
    const int* p = q + (long long)row * SHOTS;
    int sum = 0;
    for (int i = threadIdx.x; i < SHOTS; i += 256) sum += p[i];
    #pragma unroll
    for (int off = 16; off; off >>= 1) sum += __shfl_down_sync(0xffffffffu, sum, off);
    __shared__ int ssum[8];
    if ((threadIdx.x & 31) == 0) ssum[threadIdx.x >> 5] = sum;
    __syncthreads();
    if (threadIdx.x < 8) {
        int v = ssum[threadIdx.x];
        #pragma unroll
        for (int off = 4; off; off >>= 1) v += __shfl_down_sync(0xffu, v, off);
        if (threadIdx.x == 0)
            g_expect[row] = (float)v * (1.0f / (15.0f * (float)SHOTS));
    }
}

// ---------------------------------------------------------------------------
// fp32 -> fp16 converters
// ---------------------------------------------------------------------------
__global__ __launch_bounds__(256) void conv_x_kernel(const float4* __restrict__ src) {
    const int n4 = BATCH * KD / 4;
    uint2* dst = reinterpret_cast<uint2*>(g_x);
    for (int i = blockIdx.x * 256 + threadIdx.x; i < n4; i += gridDim.x * 256) {
        float4 v = src[i];
        __half2 a = __halves2half2(__float2half_rn(v.x), __float2half_rn(v.y));
        __half2 b = __halves2half2(__float2half_rn(v.z), __float2half_rn(v.w));
        uint2 hv; hv.x = *(const uint32_t*)&a; hv.y = *(const uint32_t*)&b;
        dst[i] = hv;
    }
}

__global__ __launch_bounds__(256) void conv_w_kernel(const float4* __restrict__ src) {
    const int n4 = OUT_N * KD / 4;
    uint2* dst = reinterpret_cast<uint2*>(g_w);
    for (int i = blockIdx.x * 256 + threadIdx.x; i < n4; i += gridDim.x * 256) {
        float4 v = src[i];
        __half2 a = __halves2half2(__float2half_rn(v.x), __float2half_rn(v.y));
        __half2 b = __halves2half2(__float2half_rn(v.z), __float2half_rn(v.w));
        uint2 hv; hv.x = *(const uint32_t*)&a; hv.y = *(const uint32_t*)&b;
        dst[i] = hv;
    }
}

// ---------------------------------------------------------------------------
// mma.sync fp16 GEMM: out = x W^T + bias + expect
// 128x128 tile, BK=64, 3-stage cp.async pipeline, 4 warps (2x2), 64x64/warp.
// 128 threads, 2 CTAs/SM (smem 97KB, regs <=256) to cover sync/load bubbles.
// ---------------------------------------------------------------------------
__global__ __launch_bounds__(128, 2) void gemm_kernel(const float* __restrict__ bias,
                                                      float* __restrict__ out) {
    extern __shared__ char smem_raw[];
    uint32_t sbase = (smem_to_u32(smem_raw) + 1023u) & ~1023u;
    const int tid  = threadIdx.x;
    const int wid  = tid >> 5;
    const int lane = tid & 31;

    // --- rasterization with GROUP_M supergrouping ---
    const int num_pid_n = OUT_N / BN;   // 32
    const int num_pid_m = BATCH / BM;   // 64
    const int GROUP_M = 8;
    int pid = blockIdx.x;
    int num_in_group = GROUP_M * num_pid_n;
    int group_id = pid / num_in_group;
    int first_m = group_id * GROUP_M;
    int gsz = min(num_pid_m - first_m, GROUP_M);
    int pid_m = first_m + (pid % gsz);
    int pid_n = (pid % num_in_group) / gsz;
    const int bm = pid_m * BM;
    const int bn = pid_n * BN;

    const int wm = wid & 1;     // 0..1 : 64-row band
    const int wn = wid >> 1;    // 0..1 : 64-col band

    // --- loader: 2048 16B chunks/stage, 16 per thread; indices fold to
    //     row = (tid>>3) + 16u, col byte = (tid&7)*16  (u<8 -> A, u>=8 -> B)
    const int lr8 = tid >> 3;             // 0..15
    const int lc  = tid & 7;              // 0..7
    const char* gA = (const char*)g_x + ((size_t)(bm + lr8) * KD + lc * 8) * 2;
    const char* gB = (const char*)g_w + ((size_t)(bn + lr8) * KD + lc * 8) * 2;

    auto issue_loads = [&](int j) {
        const int slot = j % STAGES;
        const uint32_t kboff = (uint32_t)j * (BK * 2);
        const uint32_t sb = sbase + slot * STAGE_BYTES;
        #pragma unroll
        for (int u = 0; u < 8; ++u) {
            uint32_t so = SWZ((uint32_t)((lr8 + 16 * u) * 128 + lc * 16));
            cp_async16(sb + so, gA + (size_t)(16 * u) * KD * 2 + kboff);
        }
        #pragma unroll
        for (int u = 0; u < 8; ++u) {
            uint32_t so = SWZ((uint32_t)((lr8 + 16 * u) * 128 + lc * 16));
            cp_async16(sb + (uint32_t)(BM * 128) + so, gB + (size_t)(16 * u) * KD * 2 + kboff);
        }
        CP_COMMIT();
    };

    // --- per-lane ldmatrix base offsets ---
    const int g  = lane >> 3;
    const int lr = lane & 7;
    const int a_row_base = wm * 64 + lr + (g & 1) * 8;   // + mi*16
    const int a_col_base = (g >> 1) * 16;                // + ks*32
    const int b_row_base = wn * 64 + lr + (g >> 1) * 8;  // + np*16
    const int b_col_base = (g & 1) * 16;                 // + ks*32

    float acc[4][8][4];
    #pragma unroll
    for (int mi = 0; mi < 4; mi++)
        #pragma unroll
        for (int ni = 0; ni < 8; ni++)
            #pragma unroll
            for (int k = 0; k < 4; k++) acc[mi][ni][k] = 0.0f;

    issue_loads(0);
    issue_loads(1);

    for (int it = 0; it < NITER; ++it) {
        const int slot = it % STAGES;
        CP_WAIT1();
        __syncthreads();

        if (it + 2 < NITER) issue_loads(it + 2);
        else                CP_COMMIT();        // empty group keeps wait count valid

        const uint32_t sA = sbase + slot * STAGE_BYTES;
        const uint32_t sB = sA + BM * 128;

        #pragma unroll
        for (int ks = 0; ks < 4; ++ks) {
            uint32_t a[4][4];
            #pragma unroll
            for (int mi = 0; mi < 4; ++mi) {
                uint32_t off = (uint32_t)((a_row_base + mi * 16) * 128 +
                                          ks * 32 + a_col_base);
                ldm_x4(a[mi], sA + SWZ(off));
            }
            uint32_t b[4][4];
            #pragma unroll
            for (int np = 0; np < 4; ++np) {
                uint32_t off = (uint32_t)((b_row_base + np * 16) * 128 +
                                          ks * 32 + b_col_base);
                ldm_x4(b[np], sB + SWZ(off));
            }
            #pragma unroll
            for (int mi = 0; mi < 4; ++mi)
                #pragma unroll
                for (int ni = 0; ni < 8; ++ni)
                    mma16816(acc[mi][ni], a[mi],
                             b[ni >> 1][2 * (ni & 1)], b[ni >> 1][2 * (ni & 1) + 1]);
        }
    }

    // --- epilogue: + bias[col] + expect[row] ---
    #pragma unroll
    for (int mi = 0; mi < 4; ++mi) {
        const int r0 = bm + wm * 64 + mi * 16 + (lane >> 2);
        const float e0 = g_expect[r0];
        const float e1 = g_expect[r0 + 8];
        float* o0 = out + (size_t)r0 * OUT_N;
        float* o1 = out + (size_t)(r0 + 8) * OUT_N;
        #pragma unroll
        for (int ni = 0; ni < 8; ++ni) {
            const int c = bn + wn * 64 + ni * 8 + (lane & 3) * 2;
            const float b0 = __ldg(&bias[c]);
            const float b1 = __ldg(&bias[c + 1]);
            float2 v0, v1;
            v0.x = acc[mi][ni][0] + b0 + e0;
            v0.y = acc[mi][ni][1] + b1 + e0;
            v1.x = acc[mi][ni][2] + b0 + e1;
            v1.y = acc[mi][ni][3] + b1 + e1;
            *(float2*)(o0 + c) = v0;
            *(float2*)(o1 + c) = v1;
        }
    }
}

// ---------------------------------------------------------------------------
extern "C" void kernel_launch(void* const* d_in, const int* in_sizes, int n_in,
                              void* d_out, int out_size) {
    const float* x    = (const float*)d_in[0];   // [8192, 4096]
    const float* W    = (const float*)d_in[1];   // [4096, 4096]
    const float* bias = (const float*)d_in[2];   // [4096]
    const int*   q    = (const int*)d_in[3];     // [8192, 1000]
    float* out = (float*)d_out;                  // [8192, 4096]

    cudaFuncSetAttribute(gemm_kernel, cudaFuncAttributeMaxDynamicSharedMemorySize, SMEM_ALLOC);

    expect_kernel<<<BATCH, 256>>>(q);
    conv_x_kernel<<<8192, 256>>>((const float4*)x);
    conv_w_kernel<<<4096, 256>>>((const float4*)W);

    const int grid = (BATCH / BM) * (OUT_N / BN);   // 2048
    gemm_kernel<<<grid, 128, SMEM_ALLOC>>>(bias, out);
}

// round 10
// speedup vs baseline: 9.3664x; 1.0366x over previous
#include <cuda_runtime.h>
#include <cuda_fp16.h>
#include <cstdint>

#define BATCH 8192
#define OUT_N 4096
#define KD    4096
#define SHOTS 1000

#define BM 128
#define BN 128
#define BK 64                       // K elems per stage (=128 bytes per row)
#define STAGES 3
#define KBLK (KD / BK)              // 64
#define NITER KBLK                  // 64
#define STAGE_BYTES (BM * 128 + BN * 128)   // 32768
#define SMEM_ALLOC (STAGES * STAGE_BYTES + 1024)   // 99328

// prep kernel block ranges
#define PX 8192
#define PW 4096
#define PE 1024                     // 8 rows per block (warp per row)

// ---- scratch (no device allocation allowed -> __device__ globals) ----
__device__ __align__(256) __half g_x[BATCH * KD];
__device__ __align__(256) __half g_w[OUT_N * KD];
__device__ float g_expect[BATCH];

// ---------------------------------------------------------------------------
__device__ __forceinline__ uint32_t smem_to_u32(const void* p) {
    uint32_t a;
    asm("{ .reg .u64 t; cvta.to.shared.u64 t, %1; cvt.u32.u64 %0, t; }" : "=r"(a) : "l"(p));
    return a;
}
#define SWZ(o) ((o) ^ (((o) >> 3) & 0x70))

__device__ __forceinline__ void cp_async16(uint32_t dst, const void* src) {
    asm volatile("cp.async.cg.shared.global [%0], [%1], 16;" :: "r"(dst), "l"(src));
}
#define CP_COMMIT() asm volatile("cp.async.commit_group;" ::: "memory")
#define CP_WAIT1()  asm volatile("cp.async.wait_group 1;"  ::: "memory")

__device__ __forceinline__ void ldm_x4(uint32_t* r, uint32_t addr) {
    asm volatile("ldmatrix.sync.aligned.m8n8.x4.shared.b16 {%0,%1,%2,%3}, [%4];"
                 : "=r"(r[0]), "=r"(r[1]), "=r"(r[2]), "=r"(r[3]) : "r"(addr));
}

__device__ __forceinline__ void mma16816(float* c, const uint32_t* a, uint32_t b0, uint32_t b1) {
    asm volatile(
        "mma.sync.aligned.m16n8k16.row.col.f32.f16.f16.f32 "
        "{%0,%1,%2,%3}, {%4,%5,%6,%7}, {%8,%9}, {%0,%1,%2,%3};"
        : "+f"(c[0]), "+f"(c[1]), "+f"(c[2]), "+f"(c[3])
        : "r"(a[0]), "r"(a[1]), "r"(a[2]), "r"(a[3]), "r"(b0), "r"(b1));
}

__device__ __forceinline__ uint2 cvt4(float4 v) {
    __half2 a = __halves2half2(__float2half_rn(v.x), __float2half_rn(v.y));
    __half2 b = __halves2half2(__float2half_rn(v.z), __float2half_rn(v.w));
    uint2 hv; hv.x = *(const uint32_t*)&a; hv.y = *(const uint32_t*)&b;
    return hv;
}

// ---------------------------------------------------------------------------
// fused prep: fp32->fp16 for x and W, plus per-row outcome expectation
// ---------------------------------------------------------------------------
__global__ __launch_bounds__(256) void prep_kernel(const float4* __restrict__ x,
                                                   const float4* __restrict__ w,
                                                   const int4* __restrict__ q) {
    const int b = blockIdx.x;
    const int tid = threadIdx.x;
    if (b < PX) {
        const int n4 = BATCH * KD / 4;
        uint2* dst = reinterpret_cast<uint2*>(g_x);
        for (int i = b * 256 + tid; i < n4; i += PX * 256)
            dst[i] = cvt4(x[i]);
    } else if (b < PX + PW) {
        const int bb = b - PX;
        const int n4 = OUT_N * KD / 4;
        uint2* dst = reinterpret_cast<uint2*>(g_w);
        for (int i = bb * 256 + tid; i < n4; i += PW * 256)
            dst[i] = cvt4(w[i]);
    } else {
        const int row  = (b - PX - PW) * 8 + (tid >> 5);   // warp per row
        const int lane = tid & 31;
        const int4* p = q + (size_t)row * (SHOTS / 4);     // 250 int4 per row
        int sum = 0;
        for (int i = lane; i < SHOTS / 4; i += 32) {
            int4 v = p[i];
            sum += v.x + v.y + v.z + v.w;
        }
        #pragma unroll
        for (int off = 16; off; off >>= 1) sum += __shfl_down_sync(0xffffffffu, sum, off);
        if (lane == 0)
            g_expect[row] = (float)sum * (1.0f / (15.0f * (float)SHOTS));
    }
}

// ---------------------------------------------------------------------------
// mma.sync fp16 GEMM: out = x W^T + bias + expect
// 128x128 tile, BK=64, 3-stage cp.async pipeline, 4 warps (2x2), 64x64/warp.
// 128 threads, 2 CTAs/SM.
// ---------------------------------------------------------------------------
__global__ __launch_bounds__(128, 2) void gemm_kernel(const float* __restrict__ bias,
                                                      float* __restrict__ out) {
    extern __shared__ char smem_raw[];
    uint32_t sbase = (smem_to_u32(smem_raw) + 1023u) & ~1023u;
    const int tid  = threadIdx.x;
    const int wid  = tid >> 5;
    const int lane = tid & 31;

    // --- rasterization with GROUP_M supergrouping ---
    const int num_pid_n = OUT_N / BN;   // 32
    const int num_pid_m = BATCH / BM;   // 64
    const int GROUP_M = 8;
    int pid = blockIdx.x;
    int num_in_group = GROUP_M * num_pid_n;
    int group_id = pid / num_in_group;
    int first_m = group_id * GROUP_M;
    int gsz = min(num_pid_m - first_m, GROUP_M);
    int pid_m = first_m + (pid % gsz);
    int pid_n = (pid % num_in_group) / gsz;
    const int bm = pid_m * BM;
    const int bn = pid_n * BN;

    const int wm = wid & 1;     // 0..1 : 64-row band
    const int wn = wid >> 1;    // 0..1 : 64-col band

    // --- loader: row = (tid>>3) + 16u, col byte = (tid&7)*16 ---
    const int lr8 = tid >> 3;             // 0..15
    const int lc  = tid & 7;              // 0..7
    const char* gA = (const char*)g_x + ((size_t)(bm + lr8) * KD + lc * 8) * 2;
    const char* gB = (const char*)g_w + ((size_t)(bn + lr8) * KD + lc * 8) * 2;

    auto issue_loads = [&](int slot, uint32_t kboff) {
        const uint32_t sb = sbase + slot * STAGE_BYTES;
        #pragma unroll
        for (int u = 0; u < 8; ++u) {
            uint32_t so = SWZ((uint32_t)((lr8 + 16 * u) * 128 + lc * 16));
            cp_async16(sb + so, gA + (size_t)(16 * u) * KD * 2 + kboff);
        }
        #pragma unroll
        for (int u = 0; u < 8; ++u) {
            uint32_t so = SWZ((uint32_t)((lr8 + 16 * u) * 128 + lc * 16));
            cp_async16(sb + (uint32_t)(BM * 128) + so, gB + (size_t)(16 * u) * KD * 2 + kboff);
        }
        CP_COMMIT();
    };

    // --- per-lane ldmatrix base offsets ---
    const int g  = lane >> 3;
    const int lr = lane & 7;
    const int a_row_base = wm * 64 + lr + (g & 1) * 8;   // + mi*16
    const int a_col_base = (g >> 1) * 16;                // + ks*32
    const int b_row_base = wn * 64 + lr + (g >> 1) * 8;  // + np*16
    const int b_col_base = (g & 1) * 16;                 // + ks*32

    float acc[4][8][4];
    #pragma unroll
    for (int mi = 0; mi < 4; mi++)
        #pragma unroll
        for (int ni = 0; ni < 8; ni++)
            #pragma unroll
            for (int k = 0; k < 4; k++) acc[mi][ni][k] = 0.0f;

    issue_loads(0, 0);
    issue_loads(1, BK * 2);

    int slot = 0;                 // stage being consumed
    int nslot = 2;                // stage to fill next
    uint32_t nkboff = 2 * BK * 2; // K-byte offset of next fill

    for (int it = 0; it < NITER; ++it) {
        CP_WAIT1();
        __syncthreads();

        if (it + 2 < NITER) {
            issue_loads(nslot, nkboff);
            nslot = (nslot == STAGES - 1) ? 0 : nslot + 1;
            nkboff += BK * 2;
        } else {
            CP_COMMIT();          // empty group keeps wait count valid
        }

        const uint32_t sA = sbase + slot * STAGE_BYTES;
        const uint32_t sB = sA + BM * 128;
        slot = (slot == STAGES - 1) ? 0 : slot + 1;

        #pragma unroll
        for (int ks = 0; ks < 4; ++ks) {
            uint32_t a[4][4];
            #pragma unroll
            for (int mi = 0; mi < 4; ++mi) {
                uint32_t off = (uint32_t)((a_row_base + mi * 16) * 128 +
                                          ks * 32 + a_col_base);
                ldm_x4(a[mi], sA + SWZ(off));
            }
            uint32_t b[4][4];
            #pragma unroll
            for (int np = 0; np < 4; ++np) {
                uint32_t off = (uint32_t)((b_row_base + np * 16) * 128 +
                                          ks * 32 + b_col_base);
                ldm_x4(b[np], sB + SWZ(off));
            }
            #pragma unroll
            for (int mi = 0; mi < 4; ++mi)
                #pragma unroll
                for (int ni = 0; ni < 8; ++ni)
                    mma16816(acc[mi][ni], a[mi],
                             b[ni >> 1][2 * (ni & 1)], b[ni >> 1][2 * (ni & 1) + 1]);
        }
    }

    // --- epilogue: + bias[col] + expect[row], bias hoisted once ---
    float bv[16];
    #pragma unroll
    for (int ni = 0; ni < 8; ++ni) {
        const int c = bn + wn * 64 + ni * 8 + (lane & 3) * 2;
        bv[2 * ni]     = __ldg(&bias[c]);
        bv[2 * ni + 1] = __ldg(&bias[c + 1]);
    }

    #pragma unroll
    for (int mi = 0; mi < 4; ++mi) {
        const int r0 = bm + wm * 64 + mi * 16 + (lane >> 2);
        const float e0 = g_expect[r0];
        const float e1 = g_expect[r0 + 8];
        float* o0 = out + (size_t)r0 * OUT_N;
        float* o1 = out + (size_t)(r0 + 8) * OUT_N;
        #pragma unroll
        for (int ni = 0; ni < 8; ++ni) {
            const int c = bn + wn * 64 + ni * 8 + (lane & 3) * 2;
            float2 v0, v1;
            v0.x = acc[mi][ni][0] + bv[2 * ni]     + e0;
            v0.y = acc[mi][ni][1] + bv[2 * ni + 1] + e0;
            v1.x = acc[mi][ni][2] + bv[2 * ni]     + e1;
            v1.y = acc[mi][ni][3] + bv[2 * ni + 1] + e1;
            *(float2*)(o0 + c) = v0;
            *(float2*)(o1 + c) = v1;
        }
    }
}

// ---------------------------------------------------------------------------
extern "C" void kernel_launch(void* const* d_in, const int* in_sizes, int n_in,
                              void* d_out, int out_size) {
    const float* x    = (const float*)d_in[0];   // [8192, 4096]
    const float* W    = (const float*)d_in[1];   // [4096, 4096]
    const float* bias = (const float*)d_in[2];   // [4096]
    const int*   q    = (const int*)d_in[3];     // [8192, 1000]
    float* out = (float*)d_out;                  // [8192, 4096]

    cudaFuncSetAttribute(gemm_kernel, cudaFuncAttributeMaxDynamicSharedMemorySize, SMEM_ALLOC);

    prep_kernel<<<PX + PW + PE, 256>>>((const float4*)x, (const float4*)W,
                                       (const int4*)q);

    const int grid = (BATCH / BM) * (OUT_N / BN);   // 2048
    gemm_kernel<<<grid, 128, SMEM_ALLOC>>>(bias, out);
}